// round 5
// baseline (speedup 1.0000x reference)
#include <cuda_runtime.h>
#include <math.h>

// ---------------------------------------------------------------------------
// MiniStageGRU on GB300 (sm_103a). Conv-GRU, convs (2,5), pad H(1,0) W(2,2).
// B=16, Cin_x=4, C=8, T=1000, F=257.
//
// Round-5:
//  - 4 output channels per thread (cog axis) -> ~half the acc registers,
//    occupancy 3 -> 4+ blocks/SM. k2 keeps BOTH gates per thread (shared loads).
//  - f-paired accumulators: FFMA2 pairs span adjacent f. Even input pairs are
//    free aligned register pairs from LDG.128; only 3 odd packs per row.
//  - weights prepacked {w,w} per co in __device__ scratch; kernels stage only
//    their own region into SMEM (LDS.128, warp-broadcast).
//  - zero_rows folded into pad_h.
// ---------------------------------------------------------------------------

typedef unsigned long long ULL;

static __device__ __forceinline__ ULL pk(float lo, float hi) {
    ULL r;
    asm("mov.b64 %0, {%1,%2};" : "=l"(r) : "f"(lo), "f"(hi));
    return r;
}
static __device__ __forceinline__ void upk(ULL v, float& lo, float& hi) {
    asm("mov.b64 {%0,%1}, %2;" : "=f"(lo), "=f"(hi) : "l"(v));
}
static __device__ __forceinline__ ULL ffma2(ULL a, ULL b, ULL c) {
    ULL d;
    asm("fma.rn.f32x2 %0, %1, %2, %3;" : "=l"(d) : "l"(a), "l"(b), "l"(c));
    return d;
}
static __device__ __forceinline__ float sigf(float x) {
    return __fdividef(1.0f, 1.0f + __expf(-x));
}
static __device__ __forceinline__ float tanh_fast(float x) {
    return __fdividef(2.0f, 1.0f + __expf(-2.0f * x)) - 1.0f;
}

constexpr int B    = 16;
constexpr int C    = 8;
constexpr int CIX  = 4;
constexpr int T    = 1000;
constexpr int TP1  = 1001;          // T+1 rows, row 0 = zeros
constexpr int F    = 257;
constexpr int FP   = 272;           // [2 left pad][257 data][13 right pad]
constexpr int CH   = TP1 * FP;
constexpr int FBLK = 65;            // f tiles of 4

constexpr int NTH_MAIN = B * T * 2 * FBLK;   // cog axis = 2

// ---- packed-weight scratch layout (ULL). weight idx within gate:
//   ((ci*2 + kh)*5 + kw)*8 + co     (ci stride 80, kh stride 40, kw stride 8)
constexpr int G1      = 0;      // k1 region: PRE(320) + BPRE(8)
constexpr int G1_B    = 320;
constexpr int G1_N    = 328;
constexpr int G2      = 328;    // k2 region
constexpr int L_XZ    = 0;
constexpr int L_XR    = 640;
constexpr int L_HZ    = 1280;
constexpr int L_HR    = 1920;
constexpr int L_BZ    = 2560;
constexpr int L_BR    = 2568;
constexpr int G2_N    = 2576;
constexpr int G3      = G2 + G2_N;  // 2904, k3 region
constexpr int L_XN    = 0;
constexpr int L_HN    = 640;
constexpr int L_BN    = 1280;
constexpr int G3_N    = 1288;
constexpr int WPK_N   = G3 + G3_N;  // 4192

// ---- device scratch --------------------------------------------------------
__device__ __align__(16) ULL   g_wpk[WPK_N];
__device__ __align__(16) float g_xpad[(size_t)B * CIX * CH];
__device__ __align__(16) float g_hpad[(size_t)B * C   * CH];
__device__ __align__(16) float g_xp  [(size_t)B * C   * CH];
__device__ __align__(16) float g_z   [(size_t)B * C   * CH];
__device__ __align__(16) float g_rh  [(size_t)B * C   * CH];

// ---- weight packing: {w,w} broadcast pairs ---------------------------------
__global__ void prep_pack(const float* __restrict__ pre_w, const float* __restrict__ pre_b,
                          const float* __restrict__ xz_w,  const float* __restrict__ xz_b,
                          const float* __restrict__ xr_w,  const float* __restrict__ xr_b,
                          const float* __restrict__ xn_w,  const float* __restrict__ xn_b,
                          const float* __restrict__ hz_w,  const float* __restrict__ hz_b,
                          const float* __restrict__ hr_w,  const float* __restrict__ hr_b,
                          const float* __restrict__ hn_w,  const float* __restrict__ hn_b)
{
    int i = blockIdx.x * blockDim.x + threadIdx.x;
    if (i >= WPK_N) return;
    float val;
    if (i < G1_B) {                                   // pre weights
        int co = i & 7; int s = i >> 3;
        int kw = s % 5; s /= 5; int kh = s & 1; int ci = s >> 1;
        val = pre_w[(co * CIX + ci) * 10 + kh * 5 + kw];
    } else if (i < G1_N) {                            // pre bias
        val = pre_b[i - G1_B];
    } else if (i < G2 + L_BZ) {                       // xz/xr/hz/hr weights
        int j = i - G2;
        int gi = j / 640, r = j % 640;
        int co = r & 7; int s = r >> 3;
        int kw = s % 5; s /= 5; int kh = s & 1; int ci = s >> 1;
        const float* w = (gi == 0) ? xz_w : (gi == 1) ? xr_w : (gi == 2) ? hz_w : hr_w;
        val = w[(co * C + ci) * 10 + kh * 5 + kw];
    } else if (i < G2 + L_BR) {                       // z bias (summed)
        int co = i - (G2 + L_BZ);
        val = xz_b[co] + hz_b[co];
    } else if (i < G2 + G2_N) {                       // r bias (summed)
        int co = i - (G2 + L_BR);
        val = xr_b[co] + hr_b[co];
    } else if (i < G3 + L_BN) {                       // xn/hn weights
        int j = i - G3;
        int gi = j / 640, r = j % 640;
        int co = r & 7; int s = r >> 3;
        int kw = s % 5; s /= 5; int kh = s & 1; int ci = s >> 1;
        const float* w = gi ? hn_w : xn_w;
        val = w[(co * C + ci) * 10 + kh * 5 + kw];
    } else {                                          // n bias (summed)
        int co = i - (G3 + L_BN);
        val = xn_b[co] + hn_b[co];
    }
    g_wpk[i] = pk(val, val);
}

// ---- f-paired window: P[m] = {row[m], row[m+1]}, m = 0..6 -------------------
static __device__ __forceinline__ void mkwin(const float* __restrict__ rowp, ULL P[7]) {
    ulonglong2 a = *reinterpret_cast<const ulonglong2*>(rowp);       // floats 0..3
    ulonglong2 b = *reinterpret_cast<const ulonglong2*>(rowp + 4);   // floats 4..7
    P[0] = a.x; P[2] = a.y; P[4] = b.x; P[6] = b.y;
    float f0, f1, f2, f3, f4, f5, f6, f7;
    upk(a.x, f0, f1); upk(a.y, f2, f3); upk(b.x, f4, f5); upk(b.y, f6, f7);
    P[1] = pk(f1, f2); P[3] = pk(f3, f4); P[5] = pk(f5, f6);
    (void)f0; (void)f7;
}

// ---- conv: one row, 4 output channels, f-paired accs ------------------------
// w points at sw[region + (ci*2+kh)*40 + co0]; acc[c][jp] = outputs
// (co0+c, f0+2jp / f0+2jp+1). Tap kw uses pair P[2jp+kw].
static __device__ __forceinline__ void conv_f(
    const ULL P[7], const ULL* __restrict__ w, ULL acc[4][2])
{
#pragma unroll
    for (int kw = 0; kw < 5; ++kw) {
        ulonglong2 wA = *reinterpret_cast<const ulonglong2*>(w + kw * 8);
        ulonglong2 wB = *reinterpret_cast<const ulonglong2*>(w + kw * 8 + 2);
        acc[0][0] = ffma2(wA.x, P[kw],     acc[0][0]);
        acc[0][1] = ffma2(wA.x, P[kw + 2], acc[0][1]);
        acc[1][0] = ffma2(wA.y, P[kw],     acc[1][0]);
        acc[1][1] = ffma2(wA.y, P[kw + 2], acc[1][1]);
        acc[2][0] = ffma2(wB.x, P[kw],     acc[2][0]);
        acc[2][1] = ffma2(wB.x, P[kw + 2], acc[2][1]);
        acc[3][0] = ffma2(wB.y, P[kw],     acc[3][0]);
        acc[3][1] = ffma2(wB.y, P[kw + 2], acc[3][1]);
    }
}

// ---- pad kernels ------------------------------------------------------------
__global__ void pad_x_kernel(const float* __restrict__ src) {
    int g = blockIdx.x * blockDim.x + threadIdx.x;
    if (g >= B * CIX * CH / 2) return;
    int e0 = g * 2;
    int fm = e0 % FP;
    int r  = e0 / FP;
    int tr = r % TP1;
    int bc = r / TP1;
    float2 v = make_float2(0.0f, 0.0f);
    if (tr > 0) {
        const float* srow = src + (bc * T + tr - 1) * F;
        int f0 = fm - 2;
        if (f0 >= 0 && f0 < F)         v.x = srow[f0];
        if (f0 + 1 >= 0 && f0 + 1 < F) v.y = srow[f0 + 1];
    }
    *reinterpret_cast<float2*>(g_xpad + e0) = v;
}
__global__ void pad_h_kernel(const float* __restrict__ src) {
    int g = blockIdx.x * blockDim.x + threadIdx.x;
    if (g >= B * C * CH / 2) return;
    int e0 = g * 2;
    int fm = e0 % FP;
    int r  = e0 / FP;
    int tr = r % TP1;
    int bc = r / TP1;
    float2 v = make_float2(0.0f, 0.0f);
    if (tr > 0) {
        const float* srow = src + (bc * T + tr - 1) * F;
        int f0 = fm - 2;
        if (f0 >= 0 && f0 < F)         v.x = srow[f0];
        if (f0 + 1 >= 0 && f0 + 1 < F) v.y = srow[f0 + 1];
    } else {
        // row 0 of intermediates must also be zero (folded zero_rows)
        *reinterpret_cast<float2*>(g_xp + e0) = v;
        *reinterpret_cast<float2*>(g_rh + e0) = v;
    }
    *reinterpret_cast<float2*>(g_hpad + e0) = v;
}

static __device__ __forceinline__ void st2(float* p, float a, float b) {
    *reinterpret_cast<float2*>(p) = make_float2(a, b);
}

// ---- K1: xp = elu(conv(x, pre)) ---------------------------------------------
__global__ void __launch_bounds__(256) k1_pre() {
    __shared__ __align__(16) ULL sw[G1_N];
    for (int i = threadIdx.x; i < G1_N; i += 256) sw[i] = g_wpk[G1 + i];
    __syncthreads();

    int g = blockIdx.x * 256 + threadIdx.x;
    if (g >= NTH_MAIN) return;
    const int fb = g % FBLK; int r1 = g / FBLK;
    const int cog = r1 & 1; r1 >>= 1;
    const int t = r1 % T, b = r1 / T;
    const int f0 = fb * 4, co0 = cog * 4;

    ULL acc[4][2];
#pragma unroll
    for (int c = 0; c < 4; ++c) {
        ULL bb = sw[G1_B + co0 + c];
        acc[c][0] = bb; acc[c][1] = bb;
    }

    int o = (b * CIX) * CH + t * FP + f0;
#pragma unroll
    for (int ci = 0; ci < CIX; ++ci) {
        ULL P[7];
        mkwin(g_xpad + o, P);
        conv_f(P, sw + ci * 80 + co0, acc);
        mkwin(g_xpad + o + FP, P);
        conv_f(P, sw + ci * 80 + 40 + co0, acc);
        o += CH;
    }

    const bool lastfb = (fb == FBLK - 1);
#pragma unroll
    for (int c = 0; c < 4; ++c) {
        float* row = g_xp + (b * C + co0 + c) * CH + (t + 1) * FP + 2 + f0;
#pragma unroll
        for (int jp = 0; jp < 2; ++jp) {
            float lo, hi;
            upk(acc[c][jp], lo, hi);
            lo = lo > 0.0f ? lo : expm1f(lo);
            hi = hi > 0.0f ? hi : expm1f(hi);
            if (f0 + 2 * jp >= F)     lo = 0.0f;
            if (f0 + 2 * jp + 1 >= F) hi = 0.0f;
            st2(row + 2 * jp, lo, hi);
        }
        if (fb == 0) st2(row - 2, 0.f, 0.f);
        if (lastfb) {
#pragma unroll
            for (int q = 4; q < 14; q += 2) st2(row + q, 0.f, 0.f);
        }
    }
}

// ---- K2: z and r*h (both gates per thread, shared input loads) ---------------
__global__ void __launch_bounds__(256) k2_zr() {
    __shared__ __align__(16) ULL sw[G2_N];
    for (int i = threadIdx.x; i < G2_N; i += 256) sw[i] = g_wpk[G2 + i];
    __syncthreads();

    int g = blockIdx.x * 256 + threadIdx.x;
    if (g >= NTH_MAIN) return;
    const int fb = g % FBLK; int r1 = g / FBLK;
    const int cog = r1 & 1; r1 >>= 1;
    const int t = r1 % T, b = r1 / T;
    const int f0 = fb * 4, co0 = cog * 4;

    ULL az[4][2], ar[4][2];
#pragma unroll
    for (int c = 0; c < 4; ++c) {
        ULL bz = sw[L_BZ + co0 + c], br = sw[L_BR + co0 + c];
        az[c][0] = bz; az[c][1] = bz;
        ar[c][0] = br; ar[c][1] = br;
    }

    int o = (b * C) * CH + t * FP + f0;
#pragma unroll 2
    for (int ci = 0; ci < C; ++ci) {
        const int wo = ci * 80 + co0;
        ULL P[7];
        mkwin(g_xp + o, P);
        conv_f(P, sw + L_XZ + wo, az);
        conv_f(P, sw + L_XR + wo, ar);
        mkwin(g_xp + o + FP, P);
        conv_f(P, sw + L_XZ + wo + 40, az);
        conv_f(P, sw + L_XR + wo + 40, ar);
        mkwin(g_hpad + o, P);
        conv_f(P, sw + L_HZ + wo, az);
        conv_f(P, sw + L_HR + wo, ar);
        mkwin(g_hpad + o + FP, P);
        conv_f(P, sw + L_HZ + wo + 40, az);
        conv_f(P, sw + L_HR + wo + 40, ar);
        o += CH;
    }

    const bool lastfb = (fb == FBLK - 1);
#pragma unroll
    for (int c = 0; c < 4; ++c) {
        const int ro = (b * C + co0 + c) * CH + (t + 1) * FP + 2 + f0;
        const float* hrow = g_hpad + ro;
        float* zrow  = g_z  + ro;
        float* rhrow = g_rh + ro;
#pragma unroll
        for (int jp = 0; jp < 2; ++jp) {
            float zlo, zhi, rlo, rhi;
            upk(az[c][jp], zlo, zhi);
            upk(ar[c][jp], rlo, rhi);
            // z: pad values never read by k3's masked output -> store raw
            st2(zrow + 2 * jp, sigf(zlo), sigf(zhi));
            // rh = r*h; h pad = 0 -> auto-zero beyond F
            float2 hh = *reinterpret_cast<const float2*>(hrow + 2 * jp);
            st2(rhrow + 2 * jp, sigf(rlo) * hh.x, sigf(rhi) * hh.y);
        }
        if (fb == 0) st2(rhrow - 2, 0.f, 0.f);
        if (lastfb) {
#pragma unroll
            for (int q = 4; q < 14; q += 2) st2(rhrow + q, 0.f, 0.f);
        }
    }
}

// ---- K3: n + output -----------------------------------------------------------
__global__ void __launch_bounds__(256) k3_out(float* __restrict__ out) {
    __shared__ __align__(16) ULL sw[G3_N];
    for (int i = threadIdx.x; i < G3_N; i += 256) sw[i] = g_wpk[G3 + i];
    __syncthreads();

    int g = blockIdx.x * 256 + threadIdx.x;
    if (g >= NTH_MAIN) return;
    const int fb = g % FBLK; int r1 = g / FBLK;
    const int cog = r1 & 1; r1 >>= 1;
    const int t = r1 % T, b = r1 / T;
    const int f0 = fb * 4, co0 = cog * 4;

    ULL an[4][2];
#pragma unroll
    for (int c = 0; c < 4; ++c) {
        ULL bn = sw[L_BN + co0 + c];
        an[c][0] = bn; an[c][1] = bn;
    }

    int o = (b * C) * CH + t * FP + f0;
#pragma unroll 2
    for (int ci = 0; ci < C; ++ci) {
        const int wo = ci * 80 + co0;
        ULL P[7];
        mkwin(g_xp + o, P);
        conv_f(P, sw + L_XN + wo, an);
        mkwin(g_xp + o + FP, P);
        conv_f(P, sw + L_XN + wo + 40, an);
        mkwin(g_rh + o, P);
        conv_f(P, sw + L_HN + wo, an);
        mkwin(g_rh + o + FP, P);
        conv_f(P, sw + L_HN + wo + 40, an);
        o += CH;
    }

#pragma unroll
    for (int c = 0; c < 4; ++c) {
        const int co = co0 + c;
        const int ro = (b * C + co) * CH + (t + 1) * FP + 2 + f0;
        const float* zrow = g_z + ro;
        const float* hrow = g_hpad + ro;
        float* orow = out + (b * C + co) * (T * F) + t * F + f0;
#pragma unroll
        for (int jp = 0; jp < 2; ++jp) {
            float nlo, nhi;
            upk(an[c][jp], nlo, nhi);
            nlo = tanh_fast(nlo); nhi = tanh_fast(nhi);
            float2 zz = *reinterpret_cast<const float2*>(zrow + 2 * jp);
            float2 hh = *reinterpret_cast<const float2*>(hrow + 2 * jp);
            int q = 2 * jp;
            if (f0 + q < F)
                orow[q] = (1.0f - zz.x) * hh.x + zz.x * nlo;
            if (f0 + q + 1 < F)
                orow[q + 1] = (1.0f - zz.y) * hh.y + zz.y * nhi;
        }
    }
}

// ---------------------------------------------------------------------------
extern "C" void kernel_launch(void* const* d_in, const int* in_sizes, int n_in,
                              void* d_out, int out_size)
{
    (void)in_sizes; (void)n_in; (void)out_size;
    const float* x = (const float*)d_in[0];
    const float* h = (const float*)d_in[1];

    prep_pack<<<(WPK_N + 255) / 256, 256>>>(
        (const float*)d_in[2],  (const float*)d_in[3],
        (const float*)d_in[4],  (const float*)d_in[5],
        (const float*)d_in[6],  (const float*)d_in[7],
        (const float*)d_in[8],  (const float*)d_in[9],
        (const float*)d_in[10], (const float*)d_in[11],
        (const float*)d_in[12], (const float*)d_in[13],
        (const float*)d_in[14], (const float*)d_in[15]);

    const int BLK = 256;
    {
        int pr = B * CIX * CH / 2;
        pad_x_kernel<<<(pr + BLK - 1) / BLK, BLK>>>(x);
    }
    {
        int pr = B * C * CH / 2;
        pad_h_kernel<<<(pr + BLK - 1) / BLK, BLK>>>(h);
    }
    const int gmain = (NTH_MAIN + BLK - 1) / BLK;
    k1_pre<<<gmain, BLK>>>();
    k2_zr <<<gmain, BLK>>>();
    k3_out<<<gmain, BLK>>>((float*)d_out);
}

// round 6
// speedup vs baseline: 1.4873x; 1.4873x over previous
#include <cuda_runtime.h>
#include <math.h>

// ---------------------------------------------------------------------------
// MiniStageGRU on GB300 (sm_103a). Conv-GRU, convs (2,5), pad H(1,0) W(2,2).
// B=16, Cin_x=4, C=8, T=1000, F=257.
//
// Round-6 = round-3 structure (8co x 4f co-paired f32x2 tile, the best so far)
// with overhead cuts:
//   - per-kernel weight regions (k1 stages 1.3KB, not 16.8KB)
//   - fast ELU (__expf)
//   - __launch_bounds__(256,4) on k1/k3
//   - single fused pad kernel
// ---------------------------------------------------------------------------

typedef unsigned long long ULL;

static __device__ __forceinline__ ULL pk(float lo, float hi) {
    ULL r;
    asm("mov.b64 %0, {%1,%2};" : "=l"(r) : "f"(lo), "f"(hi));
    return r;
}
static __device__ __forceinline__ void upk(ULL v, float& lo, float& hi) {
    asm("mov.b64 {%0,%1}, %2;" : "=f"(lo), "=f"(hi) : "l"(v));
}
static __device__ __forceinline__ ULL ffma2(ULL a, ULL b, ULL c) {
    ULL d;
    asm("fma.rn.f32x2 %0, %1, %2, %3;" : "=l"(d) : "l"(a), "l"(b), "l"(c));
    return d;
}
static __device__ __forceinline__ float sigf(float x) {
    return __fdividef(1.0f, 1.0f + __expf(-x));
}
static __device__ __forceinline__ float tanh_fast(float x) {
    return __fdividef(2.0f, 1.0f + __expf(-2.0f * x)) - 1.0f;
}

constexpr int B    = 16;
constexpr int C    = 8;
constexpr int CIX  = 4;
constexpr int T    = 1000;
constexpr int TP1  = 1001;          // T+1 rows, row 0 = zeros
constexpr int F    = 257;
constexpr int FP   = 272;           // [2 left pad][257 data][13 right pad]
constexpr int CH   = TP1 * FP;
constexpr int FBLK = 65;

constexpr int NTHREAD_MAIN = B * T * FBLK;

// ---- packed-weight regions (ULL units) -------------------------------------
// within a gate: idx = (ci*2+kh)*20 + kw*4 + p   (p = co-pair 0..3)
// K1 region: pre weights (160) + pre bias (4)
constexpr int R1      = 0;
constexpr int L1_B    = 160;
constexpr int R1_N    = 164;
// K2 region: xz, xr, hz, hr (320 each) + bz (4) + br (4)
constexpr int R2      = R1_N;
constexpr int L_XZ    = 0;
constexpr int L_XR    = 320;
constexpr int L_HZ    = 640;
constexpr int L_HR    = 960;
constexpr int L_BZ    = 1280;
constexpr int L_BR    = 1284;
constexpr int R2_N    = 1288;
// K3 region: xn, hn (320 each) + bn (4)
constexpr int R3      = R2 + R2_N;   // 1452
constexpr int L_XN    = 0;
constexpr int L_HN    = 320;
constexpr int L_BN    = 640;
constexpr int R3_N    = 644;
constexpr int WPK_N   = R3 + R3_N;   // 2096

// ---- device scratch --------------------------------------------------------
__device__ __align__(16) ULL   g_wpk[WPK_N];
__device__ __align__(16) float g_xpad[(size_t)B * CIX * CH];
__device__ __align__(16) float g_hpad[(size_t)B * C   * CH];
__device__ __align__(16) float g_xp  [(size_t)B * C   * CH];
__device__ __align__(16) float g_z   [(size_t)B * C   * CH];
__device__ __align__(16) float g_rh  [(size_t)B * C   * CH];

// ---- weight packing: f32x2 co-pairs {w[2p], w[2p+1]} ------------------------
__global__ void prep_pack(const float* __restrict__ pre_w, const float* __restrict__ pre_b,
                          const float* __restrict__ xz_w,  const float* __restrict__ xz_b,
                          const float* __restrict__ xr_w,  const float* __restrict__ xr_b,
                          const float* __restrict__ xn_w,  const float* __restrict__ xn_b,
                          const float* __restrict__ hz_w,  const float* __restrict__ hz_b,
                          const float* __restrict__ hr_w,  const float* __restrict__ hr_b,
                          const float* __restrict__ hn_w,  const float* __restrict__ hn_b)
{
    int i = blockIdx.x * blockDim.x + threadIdx.x;
    if (i >= WPK_N) return;
    ULL v;
    if (i < L1_B) {                                    // pre weights (CIN=4)
        int r = i; int p = r & 3; int s = r >> 2;
        int kw = s % 5; s /= 5; int kh = s & 1; int ci = s >> 1;
        v = pk(pre_w[((2 * p)     * CIX + ci) * 10 + kh * 5 + kw],
               pre_w[((2 * p + 1) * CIX + ci) * 10 + kh * 5 + kw]);
    } else if (i < R1_N) {                             // pre bias
        int p = i - L1_B;
        v = pk(pre_b[2 * p], pre_b[2 * p + 1]);
    } else if (i < R2 + L_BZ) {                        // xz/xr/hz/hr weights
        int j = i - R2;
        int gi = j / 320, r = j % 320;
        int p = r & 3; int s = r >> 2;
        int kw = s % 5; s /= 5; int kh = s & 1; int ci = s >> 1;
        const float* w = (gi == 0) ? xz_w : (gi == 1) ? xr_w : (gi == 2) ? hz_w : hr_w;
        v = pk(w[((2 * p)     * C + ci) * 10 + kh * 5 + kw],
               w[((2 * p + 1) * C + ci) * 10 + kh * 5 + kw]);
    } else if (i < R2 + L_BR) {                        // z bias (summed)
        int p = i - (R2 + L_BZ);
        v = pk(xz_b[2 * p] + hz_b[2 * p], xz_b[2 * p + 1] + hz_b[2 * p + 1]);
    } else if (i < R2 + R2_N) {                        // r bias (summed)
        int p = i - (R2 + L_BR);
        v = pk(xr_b[2 * p] + hr_b[2 * p], xr_b[2 * p + 1] + hr_b[2 * p + 1]);
    } else if (i < R3 + L_BN) {                        // xn/hn weights
        int j = i - R3;
        int gi = j / 320, r = j % 320;
        int p = r & 3; int s = r >> 2;
        int kw = s % 5; s /= 5; int kh = s & 1; int ci = s >> 1;
        const float* w = gi ? hn_w : xn_w;
        v = pk(w[((2 * p)     * C + ci) * 10 + kh * 5 + kw],
               w[((2 * p + 1) * C + ci) * 10 + kh * 5 + kw]);
    } else {                                           // n bias (summed)
        int p = i - (R3 + L_BN);
        v = pk(xn_b[2 * p] + hn_b[2 * p], xn_b[2 * p + 1] + hn_b[2 * p + 1]);
    }
    g_wpk[i] = v;
}

// ---- conv row micro-kernels (identical math to round 3) ---------------------
static __device__ __forceinline__ void conv_row(
    const float* __restrict__ rowp, const ULL* __restrict__ w, ULL acc[4][4])
{
    float4 A  = *reinterpret_cast<const float4*>(rowp);
    float4 Bv = *reinterpret_cast<const float4*>(rowp + 4);
    float win[8] = {A.x, A.y, A.z, A.w, Bv.x, Bv.y, Bv.z, Bv.w};
    ULL wb[8];
#pragma unroll
    for (int m = 0; m < 8; ++m) wb[m] = pk(win[m], win[m]);
#pragma unroll
    for (int kw = 0; kw < 5; ++kw) {
        ulonglong2 w01 = *reinterpret_cast<const ulonglong2*>(w + kw * 4);
        ulonglong2 w23 = *reinterpret_cast<const ulonglong2*>(w + kw * 4 + 2);
#pragma unroll
        for (int j = 0; j < 4; ++j) {
            acc[0][j] = ffma2(w01.x, wb[j + kw], acc[0][j]);
            acc[1][j] = ffma2(w01.y, wb[j + kw], acc[1][j]);
            acc[2][j] = ffma2(w23.x, wb[j + kw], acc[2][j]);
            acc[3][j] = ffma2(w23.y, wb[j + kw], acc[3][j]);
        }
    }
}

static __device__ __forceinline__ void conv_row_dual(
    const float* __restrict__ rowp,
    const ULL* __restrict__ w1, const ULL* __restrict__ w2,
    ULL a1[4][4], ULL a2[4][4])
{
    float4 A  = *reinterpret_cast<const float4*>(rowp);
    float4 Bv = *reinterpret_cast<const float4*>(rowp + 4);
    float win[8] = {A.x, A.y, A.z, A.w, Bv.x, Bv.y, Bv.z, Bv.w};
    ULL wb[8];
#pragma unroll
    for (int m = 0; m < 8; ++m) wb[m] = pk(win[m], win[m]);
#pragma unroll
    for (int kw = 0; kw < 5; ++kw) {
        ulonglong2 u01 = *reinterpret_cast<const ulonglong2*>(w1 + kw * 4);
        ulonglong2 u23 = *reinterpret_cast<const ulonglong2*>(w1 + kw * 4 + 2);
        ulonglong2 v01 = *reinterpret_cast<const ulonglong2*>(w2 + kw * 4);
        ulonglong2 v23 = *reinterpret_cast<const ulonglong2*>(w2 + kw * 4 + 2);
#pragma unroll
        for (int j = 0; j < 4; ++j) {
            a1[0][j] = ffma2(u01.x, wb[j + kw], a1[0][j]);
            a1[1][j] = ffma2(u01.y, wb[j + kw], a1[1][j]);
            a1[2][j] = ffma2(u23.x, wb[j + kw], a1[2][j]);
            a1[3][j] = ffma2(u23.y, wb[j + kw], a1[3][j]);
            a2[0][j] = ffma2(v01.x, wb[j + kw], a2[0][j]);
            a2[1][j] = ffma2(v01.y, wb[j + kw], a2[1][j]);
            a2[2][j] = ffma2(v23.x, wb[j + kw], a2[2][j]);
            a2[3][j] = ffma2(v23.y, wb[j + kw], a2[3][j]);
        }
    }
}

// ---- fused pad kernel: x, h, and zero-row-0 of intermediates ----------------
constexpr int PAD_PX = B * CIX * CH / 2;   // x float2 pairs
constexpr int PAD_PH = B * C * CH / 2;     // h float2 pairs
__global__ void pad_all(const float* __restrict__ x, const float* __restrict__ h) {
    int g = blockIdx.x * blockDim.x + threadIdx.x;
    if (g < PAD_PX) {
        int e0 = g * 2;
        int fm = e0 % FP;
        int r  = e0 / FP;
        int tr = r % TP1;
        int bc = r / TP1;
        float2 v = make_float2(0.0f, 0.0f);
        if (tr > 0) {
            const float* srow = x + (bc * T + tr - 1) * F;
            int f0 = fm - 2;
            if (f0 >= 0 && f0 < F)         v.x = srow[f0];
            if (f0 + 1 >= 0 && f0 + 1 < F) v.y = srow[f0 + 1];
        }
        *reinterpret_cast<float2*>(g_xpad + e0) = v;
    } else if (g < PAD_PX + PAD_PH) {
        int e0 = (g - PAD_PX) * 2;
        int fm = e0 % FP;
        int r  = e0 / FP;
        int tr = r % TP1;
        int bc = r / TP1;
        float2 v = make_float2(0.0f, 0.0f);
        if (tr > 0) {
            const float* srow = h + (bc * T + tr - 1) * F;
            int f0 = fm - 2;
            if (f0 >= 0 && f0 < F)         v.x = srow[f0];
            if (f0 + 1 >= 0 && f0 + 1 < F) v.y = srow[f0 + 1];
        } else {
            // zero row 0 of intermediates
            *reinterpret_cast<float2*>(g_xp + e0) = v;
            *reinterpret_cast<float2*>(g_rh + e0) = v;
        }
        *reinterpret_cast<float2*>(g_hpad + e0) = v;
    }
}

static __device__ __forceinline__ void st2(float* p, float a, float b) {
    *reinterpret_cast<float2*>(p) = make_float2(a, b);
}

// ---- K1: xp = elu(conv(x, pre)) ---------------------------------------------
__global__ void __launch_bounds__(256, 4) k1_pre() {
    __shared__ __align__(16) ULL sw[R1_N];
    for (int i = threadIdx.x; i < R1_N; i += 256) sw[i] = g_wpk[R1 + i];
    __syncthreads();

    int g = blockIdx.x * 256 + threadIdx.x;
    if (g >= NTHREAD_MAIN) return;
    const int fb = g % FBLK; int r1 = g / FBLK;
    const int t = r1 % T, b = r1 / T;
    const int f0 = fb * 4;

    ULL acc[4][4];
#pragma unroll
    for (int p = 0; p < 4; ++p) {
        ULL bb = sw[L1_B + p];
#pragma unroll
        for (int j = 0; j < 4; ++j) acc[p][j] = bb;
    }

    int o = (b * CIX) * CH + t * FP + f0;   // rows t (kh0), t+1 (kh1)
#pragma unroll
    for (int ci = 0; ci < CIX; ++ci) {
        conv_row(g_xpad + o,      sw + ci * 40,      acc);
        conv_row(g_xpad + o + FP, sw + ci * 40 + 20, acc);
        o += CH;
    }

    const bool lastfb = (fb == FBLK - 1);
#pragma unroll
    for (int p = 0; p < 4; ++p) {
        float* rowA = g_xp + (b * C + 2 * p)     * CH + (t + 1) * FP + 2 + f0;
        float* rowB = g_xp + (b * C + 2 * p + 1) * CH + (t + 1) * FP + 2 + f0;
        float v[2][4];
#pragma unroll
        for (int j = 0; j < 4; ++j) {
            float lo, hi;
            upk(acc[p][j], lo, hi);
            lo = lo > 0.0f ? lo : (__expf(lo) - 1.0f);
            hi = hi > 0.0f ? hi : (__expf(hi) - 1.0f);
            bool valid = (f0 + j) < F;
            v[0][j] = valid ? lo : 0.0f;
            v[1][j] = valid ? hi : 0.0f;
        }
        st2(rowA,     v[0][0], v[0][1]); st2(rowA + 2, v[0][2], v[0][3]);
        st2(rowB,     v[1][0], v[1][1]); st2(rowB + 2, v[1][2], v[1][3]);
        if (fb == 0) { st2(rowA - 2, 0.f, 0.f); st2(rowB - 2, 0.f, 0.f); }
        if (lastfb) {
#pragma unroll
            for (int q = 4; q < 14; q += 2) { st2(rowA + q, 0.f, 0.f); st2(rowB + q, 0.f, 0.f); }
        }
    }
}

// ---- K2: z and r*h -----------------------------------------------------------
__global__ void __launch_bounds__(256) k2_zr() {
    __shared__ __align__(16) ULL sw[R2_N];
    for (int i = threadIdx.x; i < R2_N; i += 256) sw[i] = g_wpk[R2 + i];
    __syncthreads();

    int g = blockIdx.x * 256 + threadIdx.x;
    if (g >= NTHREAD_MAIN) return;
    const int fb = g % FBLK; int r1 = g / FBLK;
    const int t = r1 % T, b = r1 / T;
    const int f0 = fb * 4;

    ULL az[4][4], ar[4][4];
#pragma unroll
    for (int p = 0; p < 4; ++p) {
        ULL bz = sw[L_BZ + p], br = sw[L_BR + p];
#pragma unroll
        for (int j = 0; j < 4; ++j) { az[p][j] = bz; ar[p][j] = br; }
    }

    int o = (b * C) * CH + t * FP + f0;
    int wo = 0;
#pragma unroll 2
    for (int ci = 0; ci < C; ++ci) {
        const float* xr = g_xp + o;
        const float* hr = g_hpad + o;
        conv_row_dual(xr,      sw + L_XZ + wo,      sw + L_XR + wo,      az, ar);
        conv_row_dual(xr + FP, sw + L_XZ + wo + 20, sw + L_XR + wo + 20, az, ar);
        conv_row_dual(hr,      sw + L_HZ + wo,      sw + L_HR + wo,      az, ar);
        conv_row_dual(hr + FP, sw + L_HZ + wo + 20, sw + L_HR + wo + 20, az, ar);
        o += CH; wo += 40;
    }

    const bool lastfb = (fb == FBLK - 1);
#pragma unroll
    for (int p = 0; p < 4; ++p) {
        float zv[2][4], rv[2][4];
#pragma unroll
        for (int j = 0; j < 4; ++j) {
            float a, bb;
            upk(az[p][j], a, bb); zv[0][j] = sigf(a); zv[1][j] = sigf(bb);
            upk(ar[p][j], a, bb); rv[0][j] = sigf(a); rv[1][j] = sigf(bb);
        }
#pragma unroll
        for (int half = 0; half < 2; ++half) {
            const int co = 2 * p + half;
            const int ro = (b * C + co) * CH + (t + 1) * FP + 2 + f0;
            const float* hrow = g_hpad + ro;
            float* zrow  = g_z  + ro;
            float* rhrow = g_rh + ro;
            float z0 = zv[half][0], z1 = zv[half][1], z2 = zv[half][2], z3 = zv[half][3];
            if (lastfb) { z1 = 0.f; z2 = 0.f; z3 = 0.f; }
            float2 h01 = *reinterpret_cast<const float2*>(hrow);
            float2 h23 = *reinterpret_cast<const float2*>(hrow + 2);
            st2(zrow,      z0, z1);
            st2(zrow + 2,  z2, z3);
            st2(rhrow,     rv[half][0] * h01.x, rv[half][1] * h01.y);
            st2(rhrow + 2, rv[half][2] * h23.x, rv[half][3] * h23.y);
            if (fb == 0) { st2(zrow - 2, 0.f, 0.f); st2(rhrow - 2, 0.f, 0.f); }
            if (lastfb) {
#pragma unroll
                for (int q = 4; q < 14; q += 2) { st2(zrow + q, 0.f, 0.f); st2(rhrow + q, 0.f, 0.f); }
            }
        }
    }
}

// ---- K3: n + output -------------------------------------------------------------
__global__ void __launch_bounds__(256, 4) k3_out(float* __restrict__ out) {
    __shared__ __align__(16) ULL sw[R3_N];
    for (int i = threadIdx.x; i < R3_N; i += 256) sw[i] = g_wpk[R3 + i];
    __syncthreads();

    int g = blockIdx.x * 256 + threadIdx.x;
    if (g >= NTHREAD_MAIN) return;
    const int fb = g % FBLK; int r1 = g / FBLK;
    const int t = r1 % T, b = r1 / T;
    const int f0 = fb * 4;

    ULL an[4][4];
#pragma unroll
    for (int p = 0; p < 4; ++p) {
        ULL bn = sw[L_BN + p];
#pragma unroll
        for (int j = 0; j < 4; ++j) an[p][j] = bn;
    }

    int o = (b * C) * CH + t * FP + f0;
    int wo = 0;
#pragma unroll 2
    for (int ci = 0; ci < C; ++ci) {
        const float* xr  = g_xp + o;
        const float* rhr = g_rh + o;
        conv_row(xr,       sw + L_XN + wo,      an);
        conv_row(xr + FP,  sw + L_XN + wo + 20, an);
        conv_row(rhr,      sw + L_HN + wo,      an);
        conv_row(rhr + FP, sw + L_HN + wo + 20, an);
        o += CH; wo += 40;
    }

#pragma unroll
    for (int p = 0; p < 4; ++p) {
        float nv[2][4];
#pragma unroll
        for (int j = 0; j < 4; ++j) {
            float a, bb;
            upk(an[p][j], a, bb);
            nv[0][j] = tanh_fast(a); nv[1][j] = tanh_fast(bb);
        }
#pragma unroll
        for (int half = 0; half < 2; ++half) {
            const int co = 2 * p + half;
            const int ro = (b * C + co) * CH + (t + 1) * FP + 2 + f0;
            const float* zrow = g_z + ro;
            const float* hrow = g_hpad + ro;
            float* orow = out + (b * C + co) * (T * F) + t * F + f0;
            float2 z01 = *reinterpret_cast<const float2*>(zrow);
            float2 z23 = *reinterpret_cast<const float2*>(zrow + 2);
            float2 h01 = *reinterpret_cast<const float2*>(hrow);
            float2 h23 = *reinterpret_cast<const float2*>(hrow + 2);
            float zz[4] = {z01.x, z01.y, z23.x, z23.y};
            float hh[4] = {h01.x, h01.y, h23.x, h23.y};
#pragma unroll
            for (int j = 0; j < 4; ++j) {
                if (f0 + j < F)
                    orow[j] = (1.0f - zz[j]) * hh[j] + zz[j] * nv[half][j];
            }
        }
    }
}

// ---------------------------------------------------------------------------
extern "C" void kernel_launch(void* const* d_in, const int* in_sizes, int n_in,
                              void* d_out, int out_size)
{
    (void)in_sizes; (void)n_in; (void)out_size;
    const float* x = (const float*)d_in[0];
    const float* h = (const float*)d_in[1];

    prep_pack<<<(WPK_N + 255) / 256, 256>>>(
        (const float*)d_in[2],  (const float*)d_in[3],
        (const float*)d_in[4],  (const float*)d_in[5],
        (const float*)d_in[6],  (const float*)d_in[7],
        (const float*)d_in[8],  (const float*)d_in[9],
        (const float*)d_in[10], (const float*)d_in[11],
        (const float*)d_in[12], (const float*)d_in[13],
        (const float*)d_in[14], (const float*)d_in[15]);

    const int BLK = 256;
    {
        int tot = PAD_PX + PAD_PH;
        pad_all<<<(tot + BLK - 1) / BLK, BLK>>>(x, h);
    }
    const int gmain = (NTHREAD_MAIN + BLK - 1) / BLK;
    k1_pre<<<gmain, BLK>>>();
    k2_zr <<<gmain, BLK>>>();
    k3_out<<<gmain, BLK>>>((float*)d_out);
}